// round 7
// baseline (speedup 1.0000x reference)
#include <cuda_runtime.h>
#include <cuda_bf16.h>
#include <stdint.h>

#define TPB   256
#define NNODE 49
#define DIM   768
#define C1    256
#define C2    128
#define NCLS  13
#define KT    16
#define NKT1  48
#define NKT2  16

#define SA 24     // A tile row stride (bf16) -> 48B rows, LDSM conflict-free
#define SB 24     // B tile row stride (bf16)
#define SH 264    // H1 row stride (bf16)    -> 528B rows, LDSM conflict-free
#define DS 65     // d1s fp32 row stride

// ---- phase-1 stage layout (byte offsets within a stage) ----
#define OFF_AHI 0
#define OFF_ALO 3072
#define OFF_BHI 6144
#define OFF_BLO 18432
#define STG     30720          // two stages: [0, 61440)
// ---- phase-2 layout (aliases phase-1; GEMM1 fully retired first) ----
#define OFF_H1HI 0             // 64 x 264 bf16 = 33792
#define OFF_H1LO 33792
#define OFF_D1S  67584         // 64 x 65 fp32 = 16640
#define OFF_B2   84224         // 2 stages x 12288
#define B2_STG   12288
// ---- persistent misc ----
#define OFF_ADJW  108800
#define OFF_ADJI  110592
#define OFF_DINV  112384
#define OFF_POOLP 112640       // 4 x 64 fp32 partials
#define OFF_POOLF 113664       // 128 fp32
#define SMEM_BYTES 114176

// ---- pre-split weights: [N][K] K-major bf16 hi/lo ----
__device__ __nv_bfloat16 g_W1hi[C1 * DIM];
__device__ __nv_bfloat16 g_W1lo[C1 * DIM];
__device__ __nv_bfloat16 g_W2hi[C2 * C1];
__device__ __nv_bfloat16 g_W2lo[C2 * C1];

__device__ __forceinline__ void mma_bf16(float* c, const unsigned* a, const unsigned* b) {
    asm volatile(
        "mma.sync.aligned.m16n8k16.row.col.f32.bf16.bf16.f32 "
        "{%0,%1,%2,%3}, {%4,%5,%6,%7}, {%8,%9}, {%0,%1,%2,%3};\n"
        : "+f"(c[0]), "+f"(c[1]), "+f"(c[2]), "+f"(c[3])
        : "r"(a[0]), "r"(a[1]), "r"(a[2]), "r"(a[3]), "r"(b[0]), "r"(b[1]));
}

__device__ __forceinline__ void ldsm4(unsigned* r, uint32_t addr) {
    asm volatile("ldmatrix.sync.aligned.m8n8.x4.shared.b16 {%0,%1,%2,%3}, [%4];"
        : "=r"(r[0]), "=r"(r[1]), "=r"(r[2]), "=r"(r[3]) : "r"(addr));
}

__device__ __forceinline__ void split2(float a, float b, unsigned& hi, unsigned& lo) {
    __nv_bfloat16 ah = __float2bfloat16(a), bh = __float2bfloat16(b);
    float ar = a - __bfloat162float(ah);
    float br = b - __bfloat162float(bh);
    __nv_bfloat16 al = __float2bfloat16(ar), bl = __float2bfloat16(br);
    hi = ((unsigned)__bfloat16_as_ushort(bh) << 16) | (unsigned)__bfloat16_as_ushort(ah);
    lo = ((unsigned)__bfloat16_as_ushort(bl) << 16) | (unsigned)__bfloat16_as_ushort(al);
}

// ==================== prep: split + transpose weights ====================
__global__ void prep_weights(const float* __restrict__ W1, const float* __restrict__ W2) {
    int idx = blockIdx.x * blockDim.x + threadIdx.x;
    if (idx < C1 * DIM) {                       // W1 [768][256] -> [256][768]
        int k = idx >> 8, n = idx & 255;
        float v = W1[idx];
        __nv_bfloat16 h = __float2bfloat16(v);
        g_W1hi[n * DIM + k] = h;
        g_W1lo[n * DIM + k] = __float2bfloat16(v - __bfloat162float(h));
    } else if (idx < C1 * DIM + C1 * C2) {      // W2 [256][128] -> [128][256]
        int j = idx - C1 * DIM;
        int k = j >> 7, n = j & 127;
        float v = W2[j];
        __nv_bfloat16 h = __float2bfloat16(v);
        g_W2hi[n * C1 + k] = h;
        g_W2lo[n * C1 + k] = __float2bfloat16(v - __bfloat162float(h));
    }
}

// =========================== main fused kernel ===========================
__global__ void __launch_bounds__(TPB, 2)
gnn_fused(const float* __restrict__ x,  const float* __restrict__ b1,
          const float* __restrict__ b2, const float* __restrict__ Wf,
          const float* __restrict__ bf, float* __restrict__ out)
{
    extern __shared__ unsigned char smem[];
    const uint32_t sbase = (uint32_t)__cvta_generic_to_shared(smem);

    float* adjw  = (float*)(smem + OFF_ADJW);
    int*   adji  = (int*)(smem + OFF_ADJI);
    float* dinv  = (float*)(smem + OFF_DINV);
    float* poolP = (float*)(smem + OFF_POOLP);
    float* poolF = (float*)(smem + OFF_POOLF);
    float* d1s   = (float*)(smem + OFF_D1S);

    const int tid  = threadIdx.x;
    const int lane = tid & 31;
    const int wid  = tid >> 5;    // 0..7
    const int wm   = wid >> 2;    // 0..1  (m32 block)
    const int wn   = wid & 3;     // 0..3  (n64 block G1 / n32 block G2)
    const int tr   = lane >> 2;
    const int tc   = lane & 3;
    const int g    = blockIdx.x;  // one graph per CTA

    // ldmatrix per-lane pattern
    const int lrow = (lane & 7) + ((lane >> 3) & 1) * 8;
    const int lkb  = (lane >> 4) * 16;

    // ---- adjacency tables (exact fp32) ----
    if (tid < NNODE) {
        int r = tid / 7, c = tid % 7;
        int nr = min(r + 1, 6) - max(r - 1, 0) + 1;
        int nc = min(c + 1, 6) - max(c - 1, 0) + 1;
        dinv[tid] = 1.0f / sqrtf((float)(nr * nc));
    }
    __syncthreads();
    if (tid < NNODE) {
        int r = tid / 7, c = tid % 7;
        float di = dinv[tid];
        int t = 0;
        for (int dr = -1; dr <= 1; dr++)
            for (int dc = -1; dc <= 1; dc++) {
                int rr = r + dr, cc = c + dc;
                if (rr >= 0 && rr < 7 && cc >= 0 && cc < 7) {
                    int j = rr * 7 + cc;
                    adji[tid * 9 + t] = j;
                    adjw[tid * 9 + t] = di * dinv[j];
                    t++;
                }
            }
        for (; t < 9; t++) { adji[tid * 9 + t] = 0; adjw[tid * 9 + t] = 0.0f; }
    }

    // =========== GEMM1: T1 = X @ W1  (64 x 256 x 768, bf16x3) ===========
    float acc[16][4];                 // [mi*8+nj], warp tile m32 x n64
    #pragma unroll
    for (int j = 0; j < 16; j++)
        #pragma unroll
        for (int k = 0; k < 4; k++) acc[j][k] = 0.0f;

    const int arow = tid >> 2;            // 0..63
    const int aq   = tid & 3;
    const bool aval = (arow < NNODE);
    const float* px = x + ((size_t)g * NNODE + arow) * DIM + aq * 4;

    int bnB[2], bkB[2];
    const __nv_bfloat16 *pW1h[2], *pW1l[2];
    #pragma unroll
    for (int s2 = 0; s2 < 2; s2++) {
        const int sl = tid + s2 * TPB;
        bnB[s2] = sl >> 1;  bkB[s2] = (sl & 1) * 8;
        pW1h[s2] = g_W1hi + (size_t)bnB[s2] * DIM + bkB[s2];
        pW1l[s2] = g_W1lo + (size_t)bnB[s2] * DIM + bkB[s2];
    }

    // frag base offsets (bytes within tile)
    const uint32_t aoff = (uint32_t)((wm * 32 + lrow) * SA * 2 + lkb);
    const uint32_t boff = (uint32_t)((wn * 64 + lrow) * SB * 2 + lkb);

    // --- prologue: stage kt=0 into buf0 ---
    {
        float4 a0 = aval ? *(const float4*)(px) : make_float4(0.f,0.f,0.f,0.f);
        unsigned h01,l01,h23,l23;
        split2(a0.x, a0.y, h01, l01); split2(a0.z, a0.w, h23, l23);
        unsigned* pA = (unsigned*)((__nv_bfloat16*)(smem + OFF_AHI) + arow*SA + aq*4);
        pA[0]=h01; pA[1]=h23;
        unsigned* pL = (unsigned*)((__nv_bfloat16*)(smem + OFF_ALO) + arow*SA + aq*4);
        pL[0]=l01; pL[1]=l23;
        #pragma unroll
        for (int s2 = 0; s2 < 2; s2++) {
            uint4 bh = *(const uint4*)(pW1h[s2]);
            uint4 bl = *(const uint4*)(pW1l[s2]);
            *(uint4*)((__nv_bfloat16*)(smem + OFF_BHI) + bnB[s2]*SB + bkB[s2]) = bh;
            *(uint4*)((__nv_bfloat16*)(smem + OFF_BLO) + bnB[s2]*SB + bkB[s2]) = bl;
        }
    }
    __syncthreads();

    #pragma unroll 1
    for (int kt = 0; kt < NKT1; kt++) {
        const uint32_t cs = (uint32_t)(kt & 1) * STG;
        const uint32_t ns = (uint32_t)((kt + 1) & 1) * STG;
        const bool more = (kt + 1 < NKT1);

        // prefetch next chunk from global (overlaps MMA block below)
        float4 aN = make_float4(0.f,0.f,0.f,0.f);
        uint4 bhN[2], blN[2];
        if (more) {
            if (aval) aN = *(const float4*)(px + (size_t)(kt+1)*KT);
            #pragma unroll
            for (int s2 = 0; s2 < 2; s2++) {
                bhN[s2] = *(const uint4*)(pW1h[s2] + (size_t)(kt+1)*KT);
                blN[s2] = *(const uint4*)(pW1l[s2] + (size_t)(kt+1)*KT);
            }
        }

        // A fragments via ldmatrix
        unsigned afh[2][4], afl[2][4];
        #pragma unroll
        for (int mi = 0; mi < 2; mi++) {
            ldsm4(afh[mi], sbase + cs + OFF_AHI + aoff + mi*16*SA*2);
            ldsm4(afl[mi], sbase + cs + OFF_ALO + aoff + mi*16*SA*2);
        }
        // B fragments: 4 pairs of n16
        #pragma unroll
        for (int p = 0; p < 4; p++) {
            unsigned bh4[4], bl4[4];
            ldsm4(bh4, sbase + cs + OFF_BHI + boff + p*16*SB*2);
            ldsm4(bl4, sbase + cs + OFF_BLO + boff + p*16*SB*2);
            #pragma unroll
            for (int h = 0; h < 2; h++) {
                const int nj = p*2 + h;
                unsigned bh[2] = { bh4[h], bh4[2+h] };
                unsigned bl[2] = { bl4[h], bl4[2+h] };
                #pragma unroll
                for (int mi = 0; mi < 2; mi++) {
                    mma_bf16(acc[mi*8+nj], afh[mi], bh);
                    mma_bf16(acc[mi*8+nj], afh[mi], bl);
                    mma_bf16(acc[mi*8+nj], afl[mi], bh);
                }
            }
        }
        if (more) {
            unsigned h01,l01,h23,l23;
            split2(aN.x, aN.y, h01, l01); split2(aN.z, aN.w, h23, l23);
            unsigned* pA = (unsigned*)((__nv_bfloat16*)(smem + ns + OFF_AHI) + arow*SA + aq*4);
            pA[0]=h01; pA[1]=h23;
            unsigned* pL = (unsigned*)((__nv_bfloat16*)(smem + ns + OFF_ALO) + arow*SA + aq*4);
            pL[0]=l01; pL[1]=l23;
            #pragma unroll
            for (int s2 = 0; s2 < 2; s2++) {
                *(uint4*)((__nv_bfloat16*)(smem + ns + OFF_BHI) + bnB[s2]*SB + bkB[s2]) = bhN[s2];
                *(uint4*)((__nv_bfloat16*)(smem + ns + OFF_BLO) + bnB[s2]*SB + bkB[s2]) = blN[s2];
            }
        }
        __syncthreads();
    }

    // ===== epilogue 1 (chunked): H1 = relu(ADJ @ T1 + b1), split bf16 hi/lo =====
    __nv_bfloat16* H1hi = (__nv_bfloat16*)(smem + OFF_H1HI);
    __nv_bfloat16* H1lo = (__nv_bfloat16*)(smem + OFF_H1LO);
    #pragma unroll 1
    for (int ci = 0; ci < 4; ci++) {
        if (wn == ci) {
            #pragma unroll
            for (int mi = 0; mi < 2; mi++)
                #pragma unroll
                for (int nj = 0; nj < 8; nj++) {
                    const int row = wm*32 + mi*16 + tr;
                    const int col = nj*8 + tc*2;
                    float* a = acc[mi*8+nj];
                    d1s[row * DS + col]           = a[0];
                    d1s[row * DS + col + 1]       = a[1];
                    d1s[(row + 8) * DS + col]     = a[2];
                    d1s[(row + 8) * DS + col + 1] = a[3];
                }
        }
        __syncthreads();
        for (int task = tid; task < NNODE * 64; task += TPB) {
            const int cl = task & 63;
            const int i  = task >> 6;
            float s = __ldg(&b1[ci * 64 + cl]);
            #pragma unroll
            for (int t = 0; t < 9; t++)
                s += adjw[i*9+t] * d1s[adji[i*9+t] * DS + cl];
            s = fmaxf(s, 0.0f);
            __nv_bfloat16 h = __float2bfloat16(s);
            H1hi[i * SH + ci*64 + cl] = h;
            H1lo[i * SH + ci*64 + cl] = __float2bfloat16(s - __bfloat162float(h));
        }
        __syncthreads();
    }

    // =========== GEMM2: T2 = H1 @ W2  (64 x 128 x 256, bf16x3) ===========
    float acc2[8][4];                 // [mi*4+nj], warp tile m32 x n32
    #pragma unroll
    for (int j = 0; j < 8; j++)
        #pragma unroll
        for (int k = 0; k < 4; k++) acc2[j][k] = 0.0f;

    const int cn = tid >> 1;          // 0..127
    const int cq = tid & 1;
    const __nv_bfloat16* pW2h = g_W2hi + (size_t)cn * C1 + cq * 8;
    const __nv_bfloat16* pW2l = g_W2lo + (size_t)cn * C1 + cq * 8;
    {
        uint4 bh = *(const uint4*)(pW2h);
        uint4 bl = *(const uint4*)(pW2l);
        *(uint4*)((__nv_bfloat16*)(smem + OFF_B2) + cn*SB + cq*8) = bh;
        *(uint4*)((__nv_bfloat16*)(smem + OFF_B2 + 6144) + cn*SB + cq*8) = bl;
    }
    __syncthreads();

    const uint32_t hoff = (uint32_t)((wm * 32 + lrow) * SH * 2 + lkb);
    const uint32_t b2off = (uint32_t)((wn * 32 + lrow) * SB * 2 + lkb);

    #pragma unroll 1
    for (int kt = 0; kt < NKT2; kt++) {
        const uint32_t cs = OFF_B2 + (uint32_t)(kt & 1) * B2_STG;
        const uint32_t ns = OFF_B2 + (uint32_t)((kt + 1) & 1) * B2_STG;
        const bool more = (kt + 1 < NKT2);
        uint4 chN, clN;
        if (more) {
            chN = *(const uint4*)(pW2h + (size_t)(kt+1)*KT);
            clN = *(const uint4*)(pW2l + (size_t)(kt+1)*KT);
        }
        unsigned afh[2][4], afl[2][4];
        #pragma unroll
        for (int mi = 0; mi < 2; mi++) {
            ldsm4(afh[mi], sbase + OFF_H1HI + hoff + mi*16*SH*2 + kt*32);
            ldsm4(afl[mi], sbase + OFF_H1LO + hoff + mi*16*SH*2 + kt*32);
        }
        #pragma unroll
        for (int p = 0; p < 2; p++) {
            unsigned bh4[4], bl4[4];
            ldsm4(bh4, sbase + cs + b2off + p*16*SB*2);
            ldsm4(bl4, sbase + cs + 6144 + b2off + p*16*SB*2);
            #pragma unroll
            for (int h = 0; h < 2; h++) {
                const int nj = p*2 + h;
                unsigned bh[2] = { bh4[h], bh4[2+h] };
                unsigned bl[2] = { bl4[h], bl4[2+h] };
                #pragma unroll
                for (int mi = 0; mi < 2; mi++) {
                    mma_bf16(acc2[mi*4+nj], afh[mi], bh);
                    mma_bf16(acc2[mi*4+nj], afh[mi], bl);
                    mma_bf16(acc2[mi*4+nj], afl[mi], bh);
                }
            }
        }
        if (more) {
            *(uint4*)((__nv_bfloat16*)(smem + ns) + cn*SB + cq*8) = chN;
            *(uint4*)((__nv_bfloat16*)(smem + ns + 6144) + cn*SB + cq*8) = clN;
        }
        __syncthreads();
    }

    // ======== epilogue 2: ADJ + bias + relu + mean-pool + head ========
    #pragma unroll 1
    for (int ci = 0; ci < 2; ci++) {
        if ((wn >> 1) == ci) {
            #pragma unroll
            for (int mi = 0; mi < 2; mi++)
                #pragma unroll
                for (int nj = 0; nj < 4; nj++) {
                    const int row = wm*32 + mi*16 + tr;
                    const int col = (wn & 1)*32 + nj*8 + tc*2;
                    float* a = acc2[mi*4+nj];
                    d1s[row * DS + col]           = a[0];
                    d1s[row * DS + col + 1]       = a[1];
                    d1s[(row + 8) * DS + col]     = a[2];
                    d1s[(row + 8) * DS + col + 1] = a[3];
                }
        }
        __syncthreads();
        {
            const int q  = tid >> 6;        // 0..3
            const int cl = tid & 63;
            const float bias = __ldg(&b2[ci * 64 + cl]);
            const int i0   = q * 13;
            const int icnt = (q < 3) ? 13 : 10;
            float ps = 0.0f;
            for (int ii = 0; ii < icnt; ii++) {
                const int i = i0 + ii;
                float s = bias;
                #pragma unroll
                for (int t = 0; t < 9; t++)
                    s += adjw[i*9+t] * d1s[adji[i*9+t] * DS + cl];
                ps += fmaxf(s, 0.0f);
            }
            poolP[q * 64 + cl] = ps;
        }
        __syncthreads();
        if (tid < 64)
            poolF[ci * 64 + tid] = (poolP[tid] + poolP[64 + tid] +
                                    poolP[128 + tid] + poolP[192 + tid]) * (1.0f / 49.0f);
        __syncthreads();
    }

    if (tid < NCLS) {
        float s = __ldg(&bf[tid]);
        #pragma unroll 8
        for (int k = 0; k < C2; k++) s += poolF[k] * __ldg(&Wf[k * NCLS + tid]);
        out[(size_t)g * NCLS + tid] = s;
    }
}

extern "C" void kernel_launch(void* const* d_in, const int* in_sizes, int n_in,
                              void* d_out, int out_size)
{
    const float* x  = (const float*)d_in[0];
    const float* W1 = (const float*)d_in[1];
    const float* b1 = (const float*)d_in[2];
    const float* W2 = (const float*)d_in[3];
    const float* b2 = (const float*)d_in[4];
    const float* Wf = (const float*)d_in[5];
    const float* bf = (const float*)d_in[6];
    float* out = (float*)d_out;

    const int B = in_sizes[0] / (NNODE * DIM);   // 4096

    prep_weights<<<(C1 * DIM + C1 * C2 + 255) / 256, 256>>>(W1, W2);

    cudaFuncSetAttribute(gnn_fused, cudaFuncAttributeMaxDynamicSharedMemorySize, SMEM_BYTES);
    gnn_fused<<<B, TPB, SMEM_BYTES>>>(x, b1, b2, Wf, bf, out);
}

// round 8
// speedup vs baseline: 1.1618x; 1.1618x over previous
#include <cuda_runtime.h>
#include <cuda_bf16.h>
#include <stdint.h>

#define TPB   256
#define NNODE 49
#define BT    2
#define DIM   768
#define C1    256
#define C2    128
#define NCLS  13
#define KT    16
#define NKT1  48
#define NKT2  16

#define SA 24     // A tile row stride (bf16) -> 48B rows, LDSM conflict-free
#define SB 24     // B tile row stride (bf16)
#define SH 264    // H1 row stride (bf16)    -> 528B rows, LDSM conflict-free
#define DS 65     // d1s fp32 row stride

// ---- phase-1 stage layout (byte offsets within a stage) ----
#define OFF_AHI 0          // 128 x 24 bf16 = 6144
#define OFF_ALO 6144
#define OFF_BHI 12288      // 256 x 24 bf16 = 12288
#define OFF_BLO 24576
#define STG     36864      // two stages: [0, 73728)
// ---- phase-2 layout (aliases phase-1; GEMM1 fully retired first) ----
#define OFF_H1HI 0         // 128 x 264 bf16 = 67584
#define OFF_H1LO 67584
#define OFF_D1S  135168    // 128 x 65 fp32 = 33280
#define OFF_B2   168448    // 2 stages x 12288 (hi 6144 | lo 6144)
#define B2_STG   12288
// ---- persistent misc ----
#define OFF_ADJW 193024
#define OFF_ADJI 194816
#define OFF_DINV 196608
#define OFF_POOL 196864    // 2 x 128 fp32
#define SMEM_BYTES 197888

// ---- pre-split weights: [N][K] K-major bf16 hi/lo ----
__device__ __nv_bfloat16 g_W1hi[C1 * DIM];
__device__ __nv_bfloat16 g_W1lo[C1 * DIM];
__device__ __nv_bfloat16 g_W2hi[C2 * C1];
__device__ __nv_bfloat16 g_W2lo[C2 * C1];

__device__ __forceinline__ void mma_bf16(float* c, const unsigned* a, const unsigned* b) {
    asm volatile(
        "mma.sync.aligned.m16n8k16.row.col.f32.bf16.bf16.f32 "
        "{%0,%1,%2,%3}, {%4,%5,%6,%7}, {%8,%9}, {%0,%1,%2,%3};\n"
        : "+f"(c[0]), "+f"(c[1]), "+f"(c[2]), "+f"(c[3])
        : "r"(a[0]), "r"(a[1]), "r"(a[2]), "r"(a[3]), "r"(b[0]), "r"(b[1]));
}

__device__ __forceinline__ void ldsm4(unsigned* r, uint32_t addr) {
    asm volatile("ldmatrix.sync.aligned.m8n8.x4.shared.b16 {%0,%1,%2,%3}, [%4];"
        : "=r"(r[0]), "=r"(r[1]), "=r"(r[2]), "=r"(r[3]) : "r"(addr));
}

__device__ __forceinline__ void cpa16(uint32_t dst, const void* src) {
    asm volatile("cp.async.cg.shared.global [%0], [%1], 16;" :: "r"(dst), "l"(src));
}
#define CPA_COMMIT() asm volatile("cp.async.commit_group;" ::: "memory")
#define CPA_WAIT0()  asm volatile("cp.async.wait_group 0;" ::: "memory")

__device__ __forceinline__ void split2(float a, float b, unsigned& hi, unsigned& lo) {
    __nv_bfloat16 ah = __float2bfloat16(a), bh = __float2bfloat16(b);
    float ar = a - __bfloat162float(ah);
    float br = b - __bfloat162float(bh);
    __nv_bfloat16 al = __float2bfloat16(ar), bl = __float2bfloat16(br);
    hi = ((unsigned)__bfloat16_as_ushort(bh) << 16) | (unsigned)__bfloat16_as_ushort(ah);
    lo = ((unsigned)__bfloat16_as_ushort(bl) << 16) | (unsigned)__bfloat16_as_ushort(al);
}

// ==================== prep: split + transpose weights ====================
__global__ void prep_weights(const float* __restrict__ W1, const float* __restrict__ W2) {
    int idx = blockIdx.x * blockDim.x + threadIdx.x;
    if (idx < C1 * DIM) {                       // W1 [768][256] -> [256][768]
        int k = idx >> 8, n = idx & 255;
        float v = W1[idx];
        __nv_bfloat16 h = __float2bfloat16(v);
        g_W1hi[n * DIM + k] = h;
        g_W1lo[n * DIM + k] = __float2bfloat16(v - __bfloat162float(h));
    } else if (idx < C1 * DIM + C1 * C2) {      // W2 [256][128] -> [128][256]
        int j = idx - C1 * DIM;
        int k = j >> 7, n = j & 127;
        float v = W2[j];
        __nv_bfloat16 h = __float2bfloat16(v);
        g_W2hi[n * C1 + k] = h;
        g_W2lo[n * C1 + k] = __float2bfloat16(v - __bfloat162float(h));
    }
}

// =========================== main fused kernel ===========================
__global__ void __launch_bounds__(TPB, 1)
gnn_fused(const float* __restrict__ x,  const float* __restrict__ b1,
          const float* __restrict__ b2, const float* __restrict__ Wf,
          const float* __restrict__ bf, float* __restrict__ out)
{
    extern __shared__ unsigned char smem[];
    const uint32_t sbase = (uint32_t)__cvta_generic_to_shared(smem);

    float* adjw   = (float*)(smem + OFF_ADJW);
    int*   adji   = (int*)(smem + OFF_ADJI);
    float* dinv   = (float*)(smem + OFF_DINV);
    float* pooled = (float*)(smem + OFF_POOL);
    float* d1s    = (float*)(smem + OFF_D1S);

    const int tid  = threadIdx.x;
    const int lane = tid & 31;
    const int wid  = tid >> 5;    // 0..7
    const int wm   = wid >> 2;    // 0..1  (m64 block)
    const int wn   = wid & 3;     // 0..3  (n64 block G1 / n32 block G2)
    const int tr   = lane >> 2;
    const int tc   = lane & 3;
    const int b0   = blockIdx.x * BT;

    // ldmatrix per-lane pattern
    const int lrow = (lane & 7) + ((lane >> 3) & 1) * 8;
    const int lkb  = (lane >> 4) * 16;

    // ---- adjacency tables (exact fp32) ----
    if (tid < NNODE) {
        int r = tid / 7, c = tid % 7;
        int nr = min(r + 1, 6) - max(r - 1, 0) + 1;
        int nc = min(c + 1, 6) - max(c - 1, 0) + 1;
        dinv[tid] = 1.0f / sqrtf((float)(nr * nc));
    }
    __syncthreads();
    if (tid < NNODE) {
        int r = tid / 7, c = tid % 7;
        float di = dinv[tid];
        int t = 0;
        for (int dr = -1; dr <= 1; dr++)
            for (int dc = -1; dc <= 1; dc++) {
                int rr = r + dr, cc = c + dc;
                if (rr >= 0 && rr < 7 && cc >= 0 && cc < 7) {
                    int j = rr * 7 + cc;
                    adji[tid * 9 + t] = j;
                    adjw[tid * 9 + t] = di * dinv[j];
                    t++;
                }
            }
        for (; t < 9; t++) { adji[tid * 9 + t] = 0; adjw[tid * 9 + t] = 0.0f; }
    }

    // =========== GEMM1: T1 = X @ W1  (128 x 256 x 768, bf16x3) ===========
    float acc[32][4];                 // [mi*8+nj], warp tile m64 x n64
    #pragma unroll
    for (int j = 0; j < 32; j++)
        #pragma unroll
        for (int k = 0; k < 4; k++) acc[j][k] = 0.0f;

    // A staging: 2 slots per thread (128 rows x 4 quads = 512 slots)
    int   arowA[2], aqA[2];
    bool  avalA[2];
    const float* pxA[2];
    #pragma unroll
    for (int s2 = 0; s2 < 2; s2++) {
        const int sl = tid + s2 * TPB;
        arowA[s2] = sl >> 2;  aqA[s2] = sl & 3;
        const int ag = arowA[s2] >> 6, anode = arowA[s2] & 63;
        avalA[s2] = (anode < NNODE);
        pxA[s2] = x + ((size_t)(b0 + ag) * NNODE + anode) * DIM + aqA[s2] * 4;
    }
    // W1 staging via cp.async: 2 chunk slots per thread for hi (and same for lo)
    int wnr[2], wcc[2];
    #pragma unroll
    for (int s2 = 0; s2 < 2; s2++) {
        const int u = tid + s2 * TPB;     // 0..511
        wnr[s2] = u >> 1;  wcc[s2] = u & 1;
    }

    // frag base byte offsets within tiles
    const uint32_t aoff = (uint32_t)((wm * 64 + lrow) * SA * 2 + lkb);
    const uint32_t boff = (uint32_t)((wn * 64 + lrow) * SB * 2 + lkb);

    // --- prologue: stage kt=0 into buf0 ---
    #pragma unroll
    for (int s2 = 0; s2 < 2; s2++) {
        float4 a0 = avalA[s2] ? *(const float4*)(pxA[s2]) : make_float4(0.f,0.f,0.f,0.f);
        unsigned h01,l01,h23,l23;
        split2(a0.x, a0.y, h01, l01); split2(a0.z, a0.w, h23, l23);
        unsigned* pA = (unsigned*)((__nv_bfloat16*)(smem + OFF_AHI) + arowA[s2]*SA + aqA[s2]*4);
        pA[0]=h01; pA[1]=h23;
        unsigned* pL = (unsigned*)((__nv_bfloat16*)(smem + OFF_ALO) + arowA[s2]*SA + aqA[s2]*4);
        pL[0]=l01; pL[1]=l23;
        const uint32_t wd = (uint32_t)(wnr[s2]*SB + wcc[s2]*8) * 2;
        cpa16(sbase + OFF_BHI + wd, g_W1hi + (size_t)wnr[s2]*DIM + wcc[s2]*8);
        cpa16(sbase + OFF_BLO + wd, g_W1lo + (size_t)wnr[s2]*DIM + wcc[s2]*8);
    }
    CPA_COMMIT();
    // prefetch A(kt=1) into regs
    float4 aN[2];
    #pragma unroll
    for (int s2 = 0; s2 < 2; s2++)
        aN[s2] = avalA[s2] ? *(const float4*)(pxA[s2] + KT) : make_float4(0.f,0.f,0.f,0.f);

    #pragma unroll 1
    for (int kt = 0; kt < NKT1; kt++) {
        const uint32_t cs = (uint32_t)(kt & 1) * STG;
        const uint32_t ns = (uint32_t)((kt + 1) & 1) * STG;
        CPA_WAIT0();
        __syncthreads();
        // issue next stage BEFORE compute (overlaps full MMA block)
        if (kt + 1 < NKT1) {
            #pragma unroll
            for (int s2 = 0; s2 < 2; s2++) {
                const uint32_t wd = (uint32_t)(wnr[s2]*SB + wcc[s2]*8) * 2;
                const size_t gsrc = (size_t)wnr[s2]*DIM + (size_t)(kt+1)*KT + wcc[s2]*8;
                cpa16(sbase + ns + OFF_BHI + wd, g_W1hi + gsrc);
                cpa16(sbase + ns + OFF_BLO + wd, g_W1lo + gsrc);
                unsigned h01,l01,h23,l23;
                split2(aN[s2].x, aN[s2].y, h01, l01);
                split2(aN[s2].z, aN[s2].w, h23, l23);
                unsigned* pA = (unsigned*)((__nv_bfloat16*)(smem + ns + OFF_AHI) + arowA[s2]*SA + aqA[s2]*4);
                pA[0]=h01; pA[1]=h23;
                unsigned* pL = (unsigned*)((__nv_bfloat16*)(smem + ns + OFF_ALO) + arowA[s2]*SA + aqA[s2]*4);
                pL[0]=l01; pL[1]=l23;
            }
            CPA_COMMIT();
            if (kt + 2 < NKT1) {
                #pragma unroll
                for (int s2 = 0; s2 < 2; s2++)
                    aN[s2] = avalA[s2] ? *(const float4*)(pxA[s2] + (size_t)(kt+2)*KT)
                                       : make_float4(0.f,0.f,0.f,0.f);
            }
        }
        // A fragments via ldmatrix
        unsigned afh[4][4], afl[4][4];
        #pragma unroll
        for (int mi = 0; mi < 4; mi++) {
            ldsm4(afh[mi], sbase + cs + OFF_AHI + aoff + mi*16*SA*2);
            ldsm4(afl[mi], sbase + cs + OFF_ALO + aoff + mi*16*SA*2);
        }
        #pragma unroll
        for (int p = 0; p < 4; p++) {
            unsigned bh4[4], bl4[4];
            ldsm4(bh4, sbase + cs + OFF_BHI + boff + p*16*SB*2);
            ldsm4(bl4, sbase + cs + OFF_BLO + boff + p*16*SB*2);
            #pragma unroll
            for (int h = 0; h < 2; h++) {
                const int nj = p*2 + h;
                unsigned bh[2] = { bh4[h], bh4[2+h] };
                unsigned bl[2] = { bl4[h], bl4[2+h] };
                #pragma unroll
                for (int mi = 0; mi < 4; mi++) {
                    mma_bf16(acc[mi*8+nj], afh[mi], bh);
                    mma_bf16(acc[mi*8+nj], afh[mi], bl);
                    mma_bf16(acc[mi*8+nj], afl[mi], bh);
                }
            }
        }
        __syncthreads();
    }

    // ===== epilogue 1 (chunked): H1 = relu(ADJ @ T1 + b1), split bf16 hi/lo =====
    __nv_bfloat16* H1hi = (__nv_bfloat16*)(smem + OFF_H1HI);
    __nv_bfloat16* H1lo = (__nv_bfloat16*)(smem + OFF_H1LO);
    #pragma unroll 1
    for (int ci = 0; ci < 4; ci++) {
        if (wn == ci) {
            #pragma unroll
            for (int mi = 0; mi < 4; mi++)
                #pragma unroll
                for (int nj = 0; nj < 8; nj++) {
                    const int row = wm*64 + mi*16 + tr;
                    const int col = nj*8 + tc*2;
                    float* a = acc[mi*8+nj];
                    d1s[row * DS + col]           = a[0];
                    d1s[row * DS + col + 1]       = a[1];
                    d1s[(row + 8) * DS + col]     = a[2];
                    d1s[(row + 8) * DS + col + 1] = a[3];
                }
        }
        __syncthreads();
        for (int task = tid; task < BT * NNODE * 64; task += TPB) {
            const int cl   = task & 63;
            const int rest = task >> 6;
            const int g    = (rest >= NNODE) ? 1 : 0;
            const int i    = rest - g * NNODE;
            float s = __ldg(&b1[ci * 64 + cl]);
            #pragma unroll
            for (int t = 0; t < 9; t++)
                s += adjw[i*9+t] * d1s[(g*64 + adji[i*9+t]) * DS + cl];
            s = fmaxf(s, 0.0f);
            __nv_bfloat16 h = __float2bfloat16(s);
            H1hi[(g*64 + i) * SH + ci*64 + cl] = h;
            H1lo[(g*64 + i) * SH + ci*64 + cl] = __float2bfloat16(s - __bfloat162float(h));
        }
        __syncthreads();
    }

    // =========== GEMM2: T2 = H1 @ W2  (128 x 128 x 256, bf16x3) ===========
    float acc2[16][4];                // [mi*4+nj], warp tile m64 x n32
    #pragma unroll
    for (int j = 0; j < 16; j++)
        #pragma unroll
        for (int k = 0; k < 4; k++) acc2[j][k] = 0.0f;

    const int c2n = tid >> 1;         // 0..127
    const int c2c = tid & 1;
    {
        const uint32_t wd = (uint32_t)(c2n*SB + c2c*8) * 2;
        cpa16(sbase + OFF_B2 + wd,        g_W2hi + (size_t)c2n*C1 + c2c*8);
        cpa16(sbase + OFF_B2 + 6144 + wd, g_W2lo + (size_t)c2n*C1 + c2c*8);
    }
    CPA_COMMIT();

    const uint32_t hoff  = (uint32_t)((wm * 64 + lrow) * SH * 2 + lkb);
    const uint32_t b2off = (uint32_t)((wn * 32 + lrow) * SB * 2 + lkb);

    #pragma unroll 1
    for (int kt = 0; kt < NKT2; kt++) {
        const uint32_t cs = OFF_B2 + (uint32_t)(kt & 1) * B2_STG;
        const uint32_t ns = OFF_B2 + (uint32_t)((kt + 1) & 1) * B2_STG;
        CPA_WAIT0();
        __syncthreads();
        if (kt + 1 < NKT2) {
            const uint32_t wd = (uint32_t)(c2n*SB + c2c*8) * 2;
            const size_t gsrc = (size_t)c2n*C1 + (size_t)(kt+1)*KT + c2c*8;
            cpa16(sbase + ns + wd,        g_W2hi + gsrc);
            cpa16(sbase + ns + 6144 + wd, g_W2lo + gsrc);
            CPA_COMMIT();
        }
        unsigned afh[4][4], afl[4][4];
        #pragma unroll
        for (int mi = 0; mi < 4; mi++) {
            ldsm4(afh[mi], sbase + OFF_H1HI + hoff + mi*16*SH*2 + kt*32);
            ldsm4(afl[mi], sbase + OFF_H1LO + hoff + mi*16*SH*2 + kt*32);
        }
        #pragma unroll
        for (int p = 0; p < 2; p++) {
            unsigned bh4[4], bl4[4];
            ldsm4(bh4, sbase + cs + b2off + p*16*SB*2);
            ldsm4(bl4, sbase + cs + 6144 + b2off + p*16*SB*2);
            #pragma unroll
            for (int h = 0; h < 2; h++) {
                const int nj = p*2 + h;
                unsigned bh[2] = { bh4[h], bh4[2+h] };
                unsigned bl[2] = { bl4[h], bl4[2+h] };
                #pragma unroll
                for (int mi = 0; mi < 4; mi++) {
                    mma_bf16(acc2[mi*4+nj], afh[mi], bh);
                    mma_bf16(acc2[mi*4+nj], afh[mi], bl);
                    mma_bf16(acc2[mi*4+nj], afl[mi], bh);
                }
            }
        }
        __syncthreads();
    }

    // ======== epilogue 2: ADJ + bias + relu + mean-pool + head ========
    #pragma unroll 1
    for (int ci = 0; ci < 2; ci++) {
        if ((wn >> 1) == ci) {
            #pragma unroll
            for (int mi = 0; mi < 4; mi++)
                #pragma unroll
                for (int nj = 0; nj < 4; nj++) {
                    const int row = wm*64 + mi*16 + tr;
                    const int col = (wn & 1)*32 + nj*8 + tc*2;
                    float* a = acc2[mi*4+nj];
                    d1s[row * DS + col]           = a[0];
                    d1s[row * DS + col + 1]       = a[1];
                    d1s[(row + 8) * DS + col]     = a[2];
                    d1s[(row + 8) * DS + col + 1] = a[3];
                }
        }
        __syncthreads();
        {
            const int half = tid & 1;
            const int rest = tid >> 1;          // 0..127
            const int g    = rest >> 6;
            const int cl   = rest & 63;
            const float bias = __ldg(&b2[ci * 64 + cl]);
            const int i0   = half * 25;
            const int icnt = half ? 24 : 25;
            float ps = 0.0f;
            for (int ii = 0; ii < icnt; ii++) {
                const int i = i0 + ii;
                float s = bias;
                #pragma unroll
                for (int t = 0; t < 9; t++)
                    s += adjw[i*9+t] * d1s[(g*64 + adji[i*9+t]) * DS + cl];
                ps += fmaxf(s, 0.0f);
            }
            ps += __shfl_xor_sync(0xFFFFFFFFu, ps, 1);
            if (half == 0) pooled[g * C2 + ci * 64 + cl] = ps * (1.0f / 49.0f);
        }
        __syncthreads();
    }

    if (tid < BT * NCLS) {
        const int g = tid / NCLS, o = tid - g * NCLS;
        float s = __ldg(&bf[o]);
        const float* pp = pooled + g * C2;
        #pragma unroll 8
        for (int k = 0; k < C2; k++) s += pp[k] * __ldg(&Wf[k * NCLS + o]);
        out[(size_t)(b0 + g) * NCLS + o] = s;
    }
}

extern "C" void kernel_launch(void* const* d_in, const int* in_sizes, int n_in,
                              void* d_out, int out_size)
{
    const float* x  = (const float*)d_in[0];
    const float* W1 = (const float*)d_in[1];
    const float* b1 = (const float*)d_in[2];
    const float* W2 = (const float*)d_in[3];
    const float* b2 = (const float*)d_in[4];
    const float* Wf = (const float*)d_in[5];
    const float* bf = (const float*)d_in[6];
    float* out = (float*)d_out;

    const int B = in_sizes[0] / (NNODE * DIM);   // 4096

    prep_weights<<<(C1 * DIM + C1 * C2 + 255) / 256, 256>>>(W1, W2);

    cudaFuncSetAttribute(gnn_fused, cudaFuncAttributeMaxDynamicSharedMemorySize, SMEM_BYTES);
    gnn_fused<<<B / BT, TPB, SMEM_BYTES>>>(x, b1, b2, Wf, bf, out);
}